// round 14
// baseline (speedup 1.0000x reference)
#include <cuda_runtime.h>
#include <cuda_fp16.h>

#define B_     8
#define HEADS  8
#define D_     128
#define R_     8
#define S_     4096
#define S4     (S_ / 4)
#define NSLAB  (B_ * HEADS)       // 64
#define TILES  8
#define TILE_S (S_ / TILES)       // 512
#define NSTG   4                  // d-rows per pipeline stage
#define NSTAGE 4                  // ring depth (power of 2)
#define NST    (D_ / NSTG)        // 32 stages

// ---------------- scratch ----------------
__device__ __half g_m[(size_t)NSLAB * S_ * R_];     // [slab][s][r] fp16, 4 MB
__device__ float g_colp[NSLAB * TILES * D_];        // per-tile partial column sums
__device__ float g_v[NSLAB * D_];                   // index == global output row
__device__ float g_eattn[NSLAB * S_];               // unnormalized exp per tile, 1 MB
__device__ float g_pmax[NSLAB * TILES];
__device__ float g_psum[NSLAB * TILES];

// packed f32x2 helpers
__device__ __forceinline__ float2 ffma2(float2 a, float2 b, float2 c) {
    unsigned long long ua = *reinterpret_cast<unsigned long long*>(&a);
    unsigned long long ub = *reinterpret_cast<unsigned long long*>(&b);
    unsigned long long uc = *reinterpret_cast<unsigned long long*>(&c);
    unsigned long long ud;
    asm("fma.rn.f32x2 %0, %1, %2, %3;" : "=l"(ud) : "l"(ua), "l"(ub), "l"(uc));
    return *reinterpret_cast<float2*>(&ud);
}
__device__ __forceinline__ unsigned f2h2(float a, float b) {
    __half2 h = __floats2half2_rn(a, b);
    return *reinterpret_cast<unsigned*>(&h);
}
__device__ __forceinline__ float2 h2f2(unsigned u) {
    __half2 h = *reinterpret_cast<__half2*>(&u);
    return __half22float2(h);
}
__device__ __forceinline__ unsigned smem_u32(const void* p) {
    unsigned a;
    asm("{ .reg .u64 t; cvta.to.shared.u64 t, %1; cvt.u32.u64 %0, t; }" : "=r"(a) : "l"(p));
    return a;
}
__device__ __forceinline__ void cpa16(unsigned dst, const void* src) {
    asm volatile("cp.async.cg.shared.global [%0], [%1], 16;" :: "r"(dst), "l"(src));
}
#define CPA_COMMIT() asm volatile("cp.async.commit_group;")
#define CPA_WAIT(n)  asm volatile("cp.async.wait_group %0;" :: "n"(n))

// =======================================================================================
// K1: cp.async ring (R9 ordering: wait -> read -> issue -> commit), barrier-free.
// DUPLICATED-PAIR weight table: s_wq[d*8+r] = {w,w}; 4x LDS.128 per d feed fma.f32x2
// directly as aligned register pairs (no MOV duplication).
// 512 CTAs x 128 threads; thread owns 4 consecutive s.
// smem = 32K ring + 8K weights + 8K partials = 48K -> 4 CTAs/SM.
// =======================================================================================
__global__ void __launch_bounds__(128) k1_proj(const float* __restrict__ x,
                                               const float* __restrict__ Wq)
{
    const int slab = blockIdx.x >> 3;
    const int tile = blockIdx.x & 7;
    const int h    = slab & (HEADS - 1);
    const int t    = threadIdx.x;
    const int lane = t & 31;
    const int w    = t >> 5;

    __shared__ __align__(16) float4 s_x[NSTAGE * NSTG * 128];   // 32 KB ring
    __shared__ __align__(16) float2 s_wq[D_ * R_];              // duplicated pairs, 8 KB
    __shared__ float s_part[16 * 128];                          // [p][d] transposed, 8 KB

    // duplicated-pair weight table: s_wq[d*8 + r] = {Wq[h,r,d], Wq[h,r,d]}
    const float* wqh = Wq + (size_t)h * R_ * D_;
    {
        #pragma unroll
        for (int r = 0; r < R_; r++) {
            float wv = wqh[r * D_ + t];
            s_wq[t * R_ + r] = make_float2(wv, wv);
        }
    }
    __syncthreads();

    const float4* __restrict__ xg =
        (const float4*)x + (size_t)slab * D_ * S4 + tile * (TILE_S / 4) + t;
    const unsigned sx = smem_u32(s_x);

    float2 alo[R_], ahi[R_];
    #pragma unroll
    for (int r = 0; r < R_; r++) { alo[r] = make_float2(0.f, 0.f); ahi[r] = make_float2(0.f, 0.f); }

    // prologue: stages 0..2
    #pragma unroll
    for (int ps = 0; ps < NSTAGE - 1; ps++) {
        #pragma unroll
        for (int r = 0; r < NSTG; r++)
            cpa16(sx + (unsigned)(((ps * NSTG + r) * 128 + t) * 16),
                  xg + (size_t)(ps * NSTG + r) * S4);
        CPA_COMMIT();
    }

    #pragma unroll 1
    for (int st = 0; st < NST; st++) {
        CPA_WAIT(NSTAGE - 2);
        const int slot = st & (NSTAGE - 1);

        float4 xv[NSTG];
        #pragma unroll
        for (int r = 0; r < NSTG; r++)
            xv[r] = s_x[(slot * NSTG + r) * 128 + t];

        if (st + NSTAGE - 1 < NST) {
            const int ns    = st + NSTAGE - 1;
            const int nslot = ns & (NSTAGE - 1);
            #pragma unroll
            for (int r = 0; r < NSTG; r++)
                cpa16(sx + (unsigned)(((nslot * NSTG + r) * 128 + t) * 16),
                      xg + (size_t)(ns * NSTG + r) * S4);
        }
        CPA_COMMIT();

        #pragma unroll
        for (int r = 0; r < NSTG; r++) {
            const int d = st * NSTG + r;
            float2 xl = make_float2(xv[r].x, xv[r].y);
            float2 xh = make_float2(xv[r].z, xv[r].w);

            // 4x LDS.128: each float4 = two duplicated pairs {wi,wi},{wi+1,wi+1}
            const float4* wrow = (const float4*)(s_wq + d * R_);
            float4 q0 = wrow[0];
            float4 q1 = wrow[1];
            float4 q2 = wrow[2];
            float4 q3 = wrow[3];
            float2 d0 = make_float2(q0.x, q0.y), d1 = make_float2(q0.z, q0.w);
            float2 d2 = make_float2(q1.x, q1.y), d3 = make_float2(q1.z, q1.w);
            float2 d4 = make_float2(q2.x, q2.y), d5 = make_float2(q2.z, q2.w);
            float2 d6 = make_float2(q3.x, q3.y), d7 = make_float2(q3.z, q3.w);
            alo[0] = ffma2(d0, xl, alo[0]);  ahi[0] = ffma2(d0, xh, ahi[0]);
            alo[1] = ffma2(d1, xl, alo[1]);  ahi[1] = ffma2(d1, xh, ahi[1]);
            alo[2] = ffma2(d2, xl, alo[2]);  ahi[2] = ffma2(d2, xh, ahi[2]);
            alo[3] = ffma2(d3, xl, alo[3]);  ahi[3] = ffma2(d3, xh, ahi[3]);
            alo[4] = ffma2(d4, xl, alo[4]);  ahi[4] = ffma2(d4, xh, ahi[4]);
            alo[5] = ffma2(d5, xl, alo[5]);  ahi[5] = ffma2(d5, xh, ahi[5]);
            alo[6] = ffma2(d6, xl, alo[6]);  ahi[6] = ffma2(d6, xh, ahi[6]);
            alo[7] = ffma2(d7, xl, alo[7]);  ahi[7] = ffma2(d7, xh, ahi[7]);

            float rs = (xv[r].x + xv[r].y) + (xv[r].z + xv[r].w);
            rs += __shfl_xor_sync(0xffffffffu, rs, 16);
            rs += __shfl_xor_sync(0xffffffffu, rs, 8);
            rs += __shfl_xor_sync(0xffffffffu, rs, 4);
            if (lane < 4) s_part[(w * 4 + lane) * 128 + d] = rs;
        }
    }
    __syncthreads();

    {
        float s = 0.f;
        #pragma unroll
        for (int i = 0; i < 16; i++) s += s_part[i * 128 + t];
        g_colp[(slab * TILES + tile) * D_ + t] = s;
    }

    {
        uint4* m4 = (uint4*)g_m + ((size_t)slab * S_ + (size_t)tile * TILE_S + t * 4);
        uint4 u;
        u.x = f2h2(alo[0].x, alo[1].x); u.y = f2h2(alo[2].x, alo[3].x);
        u.z = f2h2(alo[4].x, alo[5].x); u.w = f2h2(alo[6].x, alo[7].x);
        m4[0] = u;
        u.x = f2h2(alo[0].y, alo[1].y); u.y = f2h2(alo[2].y, alo[3].y);
        u.z = f2h2(alo[4].y, alo[5].y); u.w = f2h2(alo[6].y, alo[7].y);
        m4[1] = u;
        u.x = f2h2(ahi[0].x, ahi[1].x); u.y = f2h2(ahi[2].x, ahi[3].x);
        u.z = f2h2(ahi[4].x, ahi[5].x); u.w = f2h2(ahi[6].x, ahi[7].x);
        m4[2] = u;
        u.x = f2h2(ahi[0].y, ahi[1].y); u.y = f2h2(ahi[2].y, ahi[3].y);
        u.z = f2h2(ahi[4].y, ahi[5].y); u.w = f2h2(ahi[6].y, ahi[7].y);
        m4[3] = u;
    }
}

// =======================================================================================
// K23: merged k2+k3 with m-loads hoisted above the prologue (latency overlap).
// CTA = (slab, tile), 512 CTAs x 128 threads.
// =======================================================================================
__global__ void __launch_bounds__(128) k23_scores(const float* __restrict__ bq,
                                                  const float* __restrict__ Wk,
                                                  const float* __restrict__ bk,
                                                  const float* __restrict__ Wv,
                                                  const float* __restrict__ bv)
{
    const int slab = blockIdx.x >> 3;
    const int tile = blockIdx.x & 7;
    const int h    = slab & (HEADS - 1);
    const int t    = threadIdx.x;
    const int lane = t & 31;
    const int w    = t >> 5;

    __shared__ __align__(16) float s_avg[D_];
    __shared__ float s_k[R_];
    __shared__ float s_c;
    __shared__ float redm[4];
    __shared__ float reds[4];
    __shared__ float s_bmx;

    // HOISTED: issue the m-tile loads first so their L2 latency hides behind the
    // avg/k/c prologue below.
    const size_t soff = (size_t)tile * TILE_S + t * 4;
    const uint4* mA = (const uint4*)g_m + ((size_t)slab * S_ + soff);
    uint4 mpre[4];
    #pragma unroll
    for (int i = 0; i < 4; i++) mpre[i] = __ldcs(&mA[i]);

    // avg from column-sum partials (L2-resident)
    {
        float a = 0.f;
        #pragma unroll
        for (int i = 0; i < TILES; i++) a += g_colp[(slab * TILES + i) * D_ + t];
        s_avg[t] = a * (1.0f / (float)S_);
    }
    __syncthreads();

    // k[8]: warps 0-3, warp-cooperative, 2 rows per warp
    {
        const float4 av = ((const float4*)s_avg)[lane];
        #pragma unroll
        for (int rr = 0; rr < 2; rr++) {
            const int r = w * 2 + rr;
            float4 wk = ((const float4*)(Wk + ((size_t)h * R_ + r) * D_))[lane];
            float p = av.x * wk.x + av.y * wk.y + av.z * wk.z + av.w * wk.w;
            p += __shfl_xor_sync(0xffffffffu, p, 16);
            p += __shfl_xor_sync(0xffffffffu, p, 8);
            p += __shfl_xor_sync(0xffffffffu, p, 4);
            p += __shfl_xor_sync(0xffffffffu, p, 2);
            p += __shfl_xor_sync(0xffffffffu, p, 1);
            if (lane == 0) s_k[r] = p + bk[h * R_ + r];
        }
    }
    __syncthreads();
    if (t == 0) {
        float c = 0.f;
        #pragma unroll
        for (int r = 0; r < R_; r++) c += bq[h * R_ + r] * s_k[r];
        s_c = c;
    }
    __syncthreads();

    const float k0 = s_k[0], k1 = s_k[1], k2 = s_k[2], k3 = s_k[3];
    const float k4 = s_k[4], k5 = s_k[5], k6 = s_k[6], k7 = s_k[7];
    const float c  = s_c;

    float sc[4];
    float mx = -3.4e38f;
    #pragma unroll
    for (int i = 0; i < 4; i++) {
        uint4 ua = mpre[i];
        float2 p01 = h2f2(ua.x);
        float2 p23 = h2f2(ua.y);
        float2 p45 = h2f2(ua.z);
        float2 p67 = h2f2(ua.w);
        float v = c + k0 * p01.x + k1 * p01.y + k2 * p23.x + k3 * p23.y
                    + k4 * p45.x + k5 * p45.y + k6 * p67.x + k7 * p67.y;
        sc[i] = v;
        mx = fmaxf(mx, v);
    }
    #pragma unroll
    for (int o = 16; o; o >>= 1) mx = fmaxf(mx, __shfl_xor_sync(0xffffffffu, mx, o));
    if (lane == 0) redm[w] = mx;
    __syncthreads();
    if (t == 0) s_bmx = fmaxf(fmaxf(redm[0], redm[1]), fmaxf(redm[2], redm[3]));
    __syncthreads();
    const float bmx = s_bmx;

    float4 ev;
    ev.x = __expf(sc[0] - bmx); ev.y = __expf(sc[1] - bmx);
    ev.z = __expf(sc[2] - bmx); ev.w = __expf(sc[3] - bmx);
    float tot = (ev.x + ev.y) + (ev.z + ev.w);
    #pragma unroll
    for (int o = 16; o; o >>= 1) tot += __shfl_xor_sync(0xffffffffu, tot, o);
    if (lane == 0) reds[w] = tot;

    ((float4*)(g_eattn + (size_t)slab * S_ + soff))[0] = ev;

    __syncthreads();
    if (t == 0) {
        g_pmax[slab * TILES + tile] = bmx;
        g_psum[slab * TILES + tile] = (reds[0] + reds[1]) + (reds[2] + reds[3]);
    }

    // v: tiles 0-3, 32 rows each, warp-cooperative (4 warps x 8 rows)
    if (tile < 4) {
        const float4 av = ((const float4*)s_avg)[lane];
        #pragma unroll
        for (int i = 0; i < 8; i++) {
            const int e = tile * 32 + w * 8 + i;
            float4 wv = ((const float4*)(Wv + ((size_t)h * D_ + e) * D_))[lane];
            float p = av.x * wv.x + av.y * wv.y + av.z * wv.z + av.w * wv.w;
            p += __shfl_xor_sync(0xffffffffu, p, 16);
            p += __shfl_xor_sync(0xffffffffu, p, 8);
            p += __shfl_xor_sync(0xffffffffu, p, 4);
            p += __shfl_xor_sync(0xffffffffu, p, 2);
            p += __shfl_xor_sync(0xffffffffu, p, 1);
            if (lane == 0) g_v[slab * D_ + e] = p + bv[h * D_ + e];
        }
    }
}

// =======================================================================================
// K4: out[row,s] = v[row] * scale[tile(s)] * eattn[slab,s]. 8192 CTAs x 256 threads.
// =======================================================================================
__global__ void __launch_bounds__(256) k4_out(float* __restrict__ out)
{
    const int row  = blockIdx.x;
    const int slab = row >> 7;
    const int t    = threadIdx.x;

    __shared__ float s_scale[TILES];

    const float v = g_v[row];

    if (t < TILES) {
        float pm[TILES];
        float gmax = -3.4e38f;
        #pragma unroll
        for (int i = 0; i < TILES; i++) {
            pm[i] = g_pmax[slab * TILES + i];
            gmax = fmaxf(gmax, pm[i]);
        }
        float tot = 0.f;
        #pragma unroll
        for (int i = 0; i < TILES; i++)
            tot += g_psum[slab * TILES + i] * __expf(pm[i] - gmax);
        s_scale[t] = __expf(pm[t] - gmax) / tot;
    }
    __syncthreads();

    const float4* a4 = (const float4*)(g_eattn + (size_t)slab * S_);
    float4* o4 = (float4*)(out + (size_t)row * S_);

    #pragma unroll
    for (int i = 0; i < 4; i++) {
        float sc = v * s_scale[2 * i + (t >> 7)];
        float4 a = __ldg(&a4[i * 256 + t]);
        __stcs(&o4[i * 256 + t],
               make_float4(sc * a.x, sc * a.y, sc * a.z, sc * a.w));
    }
}

// =======================================================================================
extern "C" void kernel_launch(void* const* d_in, const int* in_sizes, int n_in,
                              void* d_out, int out_size)
{
    const float* x  = (const float*)d_in[0];
    const float* Wq = (const float*)d_in[1];
    const float* bq = (const float*)d_in[2];
    const float* Wk = (const float*)d_in[3];
    const float* bk = (const float*)d_in[4];
    const float* Wv = (const float*)d_in[5];
    const float* bv = (const float*)d_in[6];
    float* out = (float*)d_out;

    k1_proj<<<NSLAB * TILES, 128>>>(x, Wq);
    k23_scores<<<NSLAB * TILES, 128>>>(bq, Wk, bk, Wv, bv);
    k4_out<<<B_ * 1024, 256>>>(out);
}

// round 15
// speedup vs baseline: 1.0243x; 1.0243x over previous
#include <cuda_runtime.h>
#include <cuda_fp16.h>

#define B_     8
#define HEADS  8
#define D_     128
#define R_     8
#define S_     4096
#define S4     (S_ / 4)
#define NSLAB  (B_ * HEADS)       // 64
#define TILES  8
#define TILE_S (S_ / TILES)       // 512
#define NSTG   2                  // d-rows per pipeline stage (4 KB groups)
#define NSTAGE 8                  // ring depth (power of 2) -> wait(6), 6-7 in flight
#define NST    (D_ / NSTG)        // 64 stages

// ---------------- scratch ----------------
__device__ __half g_m[(size_t)NSLAB * S_ * R_];     // [slab][s][r] fp16, 4 MB
__device__ float g_colp[NSLAB * TILES * D_];        // per-tile partial column sums
__device__ float g_v[NSLAB * D_];                   // index == global output row
__device__ float g_eattn[NSLAB * S_];               // unnormalized exp per tile, 1 MB
__device__ float g_pmax[NSLAB * TILES];
__device__ float g_psum[NSLAB * TILES];

// packed f32x2 helpers
__device__ __forceinline__ float2 ffma2(float2 a, float2 b, float2 c) {
    unsigned long long ua = *reinterpret_cast<unsigned long long*>(&a);
    unsigned long long ub = *reinterpret_cast<unsigned long long*>(&b);
    unsigned long long uc = *reinterpret_cast<unsigned long long*>(&c);
    unsigned long long ud;
    asm("fma.rn.f32x2 %0, %1, %2, %3;" : "=l"(ud) : "l"(ua), "l"(ub), "l"(uc));
    return *reinterpret_cast<float2*>(&ud);
}
__device__ __forceinline__ unsigned f2h2(float a, float b) {
    __half2 h = __floats2half2_rn(a, b);
    return *reinterpret_cast<unsigned*>(&h);
}
__device__ __forceinline__ float2 h2f2(unsigned u) {
    __half2 h = *reinterpret_cast<__half2*>(&u);
    return __half22float2(h);
}
__device__ __forceinline__ unsigned smem_u32(const void* p) {
    unsigned a;
    asm("{ .reg .u64 t; cvta.to.shared.u64 t, %1; cvt.u32.u64 %0, t; }" : "=r"(a) : "l"(p));
    return a;
}
__device__ __forceinline__ void cpa16(unsigned dst, const void* src) {
    asm volatile("cp.async.cg.shared.global [%0], [%1], 16;" :: "r"(dst), "l"(src));
}
#define CPA_COMMIT() asm volatile("cp.async.commit_group;")
#define CPA_WAIT(n)  asm volatile("cp.async.wait_group %0;" :: "n"(n))

// =======================================================================================
// K1: cp.async ring, R13 body (packed-pair weight table, measured 26.4us) with finer
// granularity: NSTG=2 rows/stage, NSTAGE=8, wait(6) -> 6-7 4KB groups in flight.
// Barrier-free. 512 CTAs x 128 threads; thread owns 4 consecutive s.
// smem = 32K ring + 4K weights + 8K partials = 44K -> 4 CTAs/SM.
// =======================================================================================
__global__ void __launch_bounds__(128) k1_proj(const float* __restrict__ x,
                                               const float* __restrict__ Wq)
{
    const int slab = blockIdx.x >> 3;
    const int tile = blockIdx.x & 7;
    const int h    = slab & (HEADS - 1);
    const int t    = threadIdx.x;
    const int lane = t & 31;
    const int w    = t >> 5;

    __shared__ __align__(16) float4 s_x[NSTAGE * NSTG * 128];   // 32 KB ring
    __shared__ __align__(16) float2 s_wq[D_ * R_ / 2];          // packed pairs, 4 KB
    __shared__ float s_part[16 * 128];                          // [p][d] transposed, 8 KB

    // weight table: s_wq[d*4 + j] = {Wq[h,2j,d], Wq[h,2j+1,d]}  (R13 form)
    const float* wqh = Wq + (size_t)h * R_ * D_;
    {
        float w0 = wqh[0 * D_ + t], w1 = wqh[1 * D_ + t];
        float w2 = wqh[2 * D_ + t], w3 = wqh[3 * D_ + t];
        float w4 = wqh[4 * D_ + t], w5 = wqh[5 * D_ + t];
        float w6 = wqh[6 * D_ + t], w7 = wqh[7 * D_ + t];
        s_wq[t * 4 + 0] = make_float2(w0, w1);
        s_wq[t * 4 + 1] = make_float2(w2, w3);
        s_wq[t * 4 + 2] = make_float2(w4, w5);
        s_wq[t * 4 + 3] = make_float2(w6, w7);
    }
    __syncthreads();

    const float4* __restrict__ xg =
        (const float4*)x + (size_t)slab * D_ * S4 + tile * (TILE_S / 4) + t;
    const unsigned sx = smem_u32(s_x);

    float2 alo[R_], ahi[R_];
    #pragma unroll
    for (int r = 0; r < R_; r++) { alo[r] = make_float2(0.f, 0.f); ahi[r] = make_float2(0.f, 0.f); }

    // prologue: stages 0..NSTAGE-2 (7 stages = 28 KB in flight before first consume)
    #pragma unroll
    for (int ps = 0; ps < NSTAGE - 1; ps++) {
        #pragma unroll
        for (int r = 0; r < NSTG; r++)
            cpa16(sx + (unsigned)(((ps * NSTG + r) * 128 + t) * 16),
                  xg + (size_t)(ps * NSTG + r) * S4);
        CPA_COMMIT();
    }

    #pragma unroll 1
    for (int st = 0; st < NST; st++) {
        CPA_WAIT(NSTAGE - 2);
        const int slot = st & (NSTAGE - 1);

        float4 xv[NSTG];
        #pragma unroll
        for (int r = 0; r < NSTG; r++)
            xv[r] = s_x[(slot * NSTG + r) * 128 + t];

        if (st + NSTAGE - 1 < NST) {
            const int ns    = st + NSTAGE - 1;
            const int nslot = ns & (NSTAGE - 1);
            #pragma unroll
            for (int r = 0; r < NSTG; r++)
                cpa16(sx + (unsigned)(((nslot * NSTG + r) * 128 + t) * 16),
                      xg + (size_t)(ns * NSTG + r) * S4);
        }
        CPA_COMMIT();

        #pragma unroll
        for (int r = 0; r < NSTG; r++) {
            const int d = st * NSTG + r;
            float2 xl = make_float2(xv[r].x, xv[r].y);
            float2 xh = make_float2(xv[r].z, xv[r].w);

            const float4* wrow = (const float4*)(s_wq + d * 4);
            float4 wpa = wrow[0];   // {w0,w1,w2,w3}
            float4 wpb = wrow[1];   // {w4,w5,w6,w7}
            float2 d0 = make_float2(wpa.x, wpa.x);
            float2 d1 = make_float2(wpa.y, wpa.y);
            float2 d2 = make_float2(wpa.z, wpa.z);
            float2 d3 = make_float2(wpa.w, wpa.w);
            float2 d4 = make_float2(wpb.x, wpb.x);
            float2 d5 = make_float2(wpb.y, wpb.y);
            float2 d6 = make_float2(wpb.z, wpb.z);
            float2 d7 = make_float2(wpb.w, wpb.w);
            alo[0] = ffma2(d0, xl, alo[0]);  ahi[0] = ffma2(d0, xh, ahi[0]);
            alo[1] = ffma2(d1, xl, alo[1]);  ahi[1] = ffma2(d1, xh, ahi[1]);
            alo[2] = ffma2(d2, xl, alo[2]);  ahi[2] = ffma2(d2, xh, ahi[2]);
            alo[3] = ffma2(d3, xl, alo[3]);  ahi[3] = ffma2(d3, xh, ahi[3]);
            alo[4] = ffma2(d4, xl, alo[4]);  ahi[4] = ffma2(d4, xh, ahi[4]);
            alo[5] = ffma2(d5, xl, alo[5]);  ahi[5] = ffma2(d5, xh, ahi[5]);
            alo[6] = ffma2(d6, xl, alo[6]);  ahi[6] = ffma2(d6, xh, ahi[6]);
            alo[7] = ffma2(d7, xl, alo[7]);  ahi[7] = ffma2(d7, xh, ahi[7]);

            float rs = (xv[r].x + xv[r].y) + (xv[r].z + xv[r].w);
            rs += __shfl_xor_sync(0xffffffffu, rs, 16);
            rs += __shfl_xor_sync(0xffffffffu, rs, 8);
            rs += __shfl_xor_sync(0xffffffffu, rs, 4);
            if (lane < 4) s_part[(w * 4 + lane) * 128 + d] = rs;
        }
    }
    __syncthreads();

    {
        float s = 0.f;
        #pragma unroll
        for (int i = 0; i < 16; i++) s += s_part[i * 128 + t];
        g_colp[(slab * TILES + tile) * D_ + t] = s;
    }

    {
        uint4* m4 = (uint4*)g_m + ((size_t)slab * S_ + (size_t)tile * TILE_S + t * 4);
        uint4 u;
        u.x = f2h2(alo[0].x, alo[1].x); u.y = f2h2(alo[2].x, alo[3].x);
        u.z = f2h2(alo[4].x, alo[5].x); u.w = f2h2(alo[6].x, alo[7].x);
        m4[0] = u;
        u.x = f2h2(alo[0].y, alo[1].y); u.y = f2h2(alo[2].y, alo[3].y);
        u.z = f2h2(alo[4].y, alo[5].y); u.w = f2h2(alo[6].y, alo[7].y);
        m4[1] = u;
        u.x = f2h2(ahi[0].x, ahi[1].x); u.y = f2h2(ahi[2].x, ahi[3].x);
        u.z = f2h2(ahi[4].x, ahi[5].x); u.w = f2h2(ahi[6].x, ahi[7].x);
        m4[2] = u;
        u.x = f2h2(ahi[0].y, ahi[1].y); u.y = f2h2(ahi[2].y, ahi[3].y);
        u.z = f2h2(ahi[4].y, ahi[5].y); u.w = f2h2(ahi[6].y, ahi[7].y);
        m4[3] = u;
    }
}

// =======================================================================================
// K23: merged k2+k3 with m-loads hoisted above the prologue (R14 version — kept).
// CTA = (slab, tile), 512 CTAs x 128 threads.
// =======================================================================================
__global__ void __launch_bounds__(128) k23_scores(const float* __restrict__ bq,
                                                  const float* __restrict__ Wk,
                                                  const float* __restrict__ bk,
                                                  const float* __restrict__ Wv,
                                                  const float* __restrict__ bv)
{
    const int slab = blockIdx.x >> 3;
    const int tile = blockIdx.x & 7;
    const int h    = slab & (HEADS - 1);
    const int t    = threadIdx.x;
    const int lane = t & 31;
    const int w    = t >> 5;

    __shared__ __align__(16) float s_avg[D_];
    __shared__ float s_k[R_];
    __shared__ float s_c;
    __shared__ float redm[4];
    __shared__ float reds[4];
    __shared__ float s_bmx;

    // hoisted m-tile loads: L2 latency overlaps the avg/k/c prologue
    const size_t soff = (size_t)tile * TILE_S + t * 4;
    const uint4* mA = (const uint4*)g_m + ((size_t)slab * S_ + soff);
    uint4 mpre[4];
    #pragma unroll
    for (int i = 0; i < 4; i++) mpre[i] = __ldcs(&mA[i]);

    // avg from column-sum partials (L2-resident)
    {
        float a = 0.f;
        #pragma unroll
        for (int i = 0; i < TILES; i++) a += g_colp[(slab * TILES + i) * D_ + t];
        s_avg[t] = a * (1.0f / (float)S_);
    }
    __syncthreads();

    // k[8]: warps 0-3, warp-cooperative, 2 rows per warp
    {
        const float4 av = ((const float4*)s_avg)[lane];
        #pragma unroll
        for (int rr = 0; rr < 2; rr++) {
            const int r = w * 2 + rr;
            float4 wk = ((const float4*)(Wk + ((size_t)h * R_ + r) * D_))[lane];
            float p = av.x * wk.x + av.y * wk.y + av.z * wk.z + av.w * wk.w;
            p += __shfl_xor_sync(0xffffffffu, p, 16);
            p += __shfl_xor_sync(0xffffffffu, p, 8);
            p += __shfl_xor_sync(0xffffffffu, p, 4);
            p += __shfl_xor_sync(0xffffffffu, p, 2);
            p += __shfl_xor_sync(0xffffffffu, p, 1);
            if (lane == 0) s_k[r] = p + bk[h * R_ + r];
        }
    }
    __syncthreads();
    if (t == 0) {
        float c = 0.f;
        #pragma unroll
        for (int r = 0; r < R_; r++) c += bq[h * R_ + r] * s_k[r];
        s_c = c;
    }
    __syncthreads();

    const float k0 = s_k[0], k1 = s_k[1], k2 = s_k[2], k3 = s_k[3];
    const float k4 = s_k[4], k5 = s_k[5], k6 = s_k[6], k7 = s_k[7];
    const float c  = s_c;

    float sc[4];
    float mx = -3.4e38f;
    #pragma unroll
    for (int i = 0; i < 4; i++) {
        uint4 ua = mpre[i];
        float2 p01 = h2f2(ua.x);
        float2 p23 = h2f2(ua.y);
        float2 p45 = h2f2(ua.z);
        float2 p67 = h2f2(ua.w);
        float v = c + k0 * p01.x + k1 * p01.y + k2 * p23.x + k3 * p23.y
                    + k4 * p45.x + k5 * p45.y + k6 * p67.x + k7 * p67.y;
        sc[i] = v;
        mx = fmaxf(mx, v);
    }
    #pragma unroll
    for (int o = 16; o; o >>= 1) mx = fmaxf(mx, __shfl_xor_sync(0xffffffffu, mx, o));
    if (lane == 0) redm[w] = mx;
    __syncthreads();
    if (t == 0) s_bmx = fmaxf(fmaxf(redm[0], redm[1]), fmaxf(redm[2], redm[3]));
    __syncthreads();
    const float bmx = s_bmx;

    float4 ev;
    ev.x = __expf(sc[0] - bmx); ev.y = __expf(sc[1] - bmx);
    ev.z = __expf(sc[2] - bmx); ev.w = __expf(sc[3] - bmx);
    float tot = (ev.x + ev.y) + (ev.z + ev.w);
    #pragma unroll
    for (int o = 16; o; o >>= 1) tot += __shfl_xor_sync(0xffffffffu, tot, o);
    if (lane == 0) reds[w] = tot;

    ((float4*)(g_eattn + (size_t)slab * S_ + soff))[0] = ev;

    __syncthreads();
    if (t == 0) {
        g_pmax[slab * TILES + tile] = bmx;
        g_psum[slab * TILES + tile] = (reds[0] + reds[1]) + (reds[2] + reds[3]);
    }

    // v: tiles 0-3, 32 rows each, warp-cooperative (4 warps x 8 rows)
    if (tile < 4) {
        const float4 av = ((const float4*)s_avg)[lane];
        #pragma unroll
        for (int i = 0; i < 8; i++) {
            const int e = tile * 32 + w * 8 + i;
            float4 wv = ((const float4*)(Wv + ((size_t)h * D_ + e) * D_))[lane];
            float p = av.x * wv.x + av.y * wv.y + av.z * wv.z + av.w * wv.w;
            p += __shfl_xor_sync(0xffffffffu, p, 16);
            p += __shfl_xor_sync(0xffffffffu, p, 8);
            p += __shfl_xor_sync(0xffffffffu, p, 4);
            p += __shfl_xor_sync(0xffffffffu, p, 2);
            p += __shfl_xor_sync(0xffffffffu, p, 1);
            if (lane == 0) g_v[slab * D_ + e] = p + bv[h * D_ + e];
        }
    }
}

// =======================================================================================
// K4: out[row,s] = v[row] * scale[tile(s)] * eattn[slab,s]. 8192 CTAs x 256 threads.
// =======================================================================================
__global__ void __launch_bounds__(256) k4_out(float* __restrict__ out)
{
    const int row  = blockIdx.x;
    const int slab = row >> 7;
    const int t    = threadIdx.x;

    __shared__ float s_scale[TILES];

    const float v = g_v[row];

    if (t < TILES) {
        float pm[TILES];
        float gmax = -3.4e38f;
        #pragma unroll
        for (int i = 0; i < TILES; i++) {
            pm[i] = g_pmax[slab * TILES + i];
            gmax = fmaxf(gmax, pm[i]);
        }
        float tot = 0.f;
        #pragma unroll
        for (int i = 0; i < TILES; i++)
            tot += g_psum[slab * TILES + i] * __expf(pm[i] - gmax);
        s_scale[t] = __expf(pm[t] - gmax) / tot;
    }
    __syncthreads();

    const float4* a4 = (const float4*)(g_eattn + (size_t)slab * S_);
    float4* o4 = (float4*)(out + (size_t)row * S_);

    #pragma unroll
    for (int i = 0; i < 4; i++) {
        float sc = v * s_scale[2 * i + (t >> 7)];
        float4 a = __ldg(&a4[i * 256 + t]);
        __stcs(&o4[i * 256 + t],
               make_float4(sc * a.x, sc * a.y, sc * a.z, sc * a.w));
    }
}

// =======================================================================================
extern "C" void kernel_launch(void* const* d_in, const int* in_sizes, int n_in,
                              void* d_out, int out_size)
{
    const float* x  = (const float*)d_in[0];
    const float* Wq = (const float*)d_in[1];
    const float* bq = (const float*)d_in[2];
    const float* Wk = (const float*)d_in[3];
    const float* bk = (const float*)d_in[4];
    const float* Wv = (const float*)d_in[5];
    const float* bv = (const float*)d_in[6];
    float* out = (float*)d_out;

    k1_proj<<<NSLAB * TILES, 128>>>(x, Wq);
    k23_scores<<<NSLAB * TILES, 128>>>(bq, Wk, bk, Wv, bv);
    k4_out<<<B_ * 1024, 256>>>(out);
}